// round 1
// baseline (speedup 1.0000x reference)
#include <cuda_runtime.h>
#include <cstdint>

typedef unsigned long long ull;

#define E_TOT   200000
#define NBR     20
#define ES      16
#define HID     128
#define INS     32
#define OUTS    32
#define TE      128
#define NTHR    256

// ---------------------------------------------------------------------------
// Shared memory layout (all activation tiles TRANSPOSED: [feature][edge])
// ---------------------------------------------------------------------------
struct SmemT {
    float  eT[ES][TE + 4];        // e_vw transposed, padded row (132) vs conflicts
    float  hwT[INS][TE];          // gathered h_w table per edge
    float  x2T[HID][TE];          // layer-1 output
    float2 wdA[HID][OUTS];        // duplicated weight slice (f32x2: (w,w))
    float2 b2d[INS][OUTS];        // duplicated b2, indexed [i][o]
    float  sbias[HID];            // b0 then b1
    union {
        float  x1T[HID][TE];      // layer-0 output (dead after GEMM1)
        float2 wdB[HID][OUTS];    // second W2 buffer for double-buffering
    } u;
};

// ---------------------------------------------------------------------------
// packed f32x2 helpers (FFMA2 path — ptxas never auto-fuses, must be PTX)
// ---------------------------------------------------------------------------
__device__ __forceinline__ void upk2(ull v, float &lo, float &hi) {
    asm("mov.b64 {%0, %1}, %2;" : "=f"(lo), "=f"(hi) : "l"(v));
}
__device__ __forceinline__ void fma2(ull &d, ull a, ull b) {
    asm("fma.rn.f32x2 %0, %1, %2, %0;" : "+l"(d) : "l"(a), "l"(b));
}
__device__ __forceinline__ ull mul2(ull a, ull b) {
    ull r; asm("mul.rn.f32x2 %0, %1, %2;" : "=l"(r) : "l"(a), "l"(b)); return r;
}

__global__ void __launch_bounds__(NTHR, 1)
msgfunc_kernel(const float* __restrict__ h_w,
               const float* __restrict__ e_vw,
               const float* __restrict__ W0, const float* __restrict__ b0,
               const float* __restrict__ W1, const float* __restrict__ b1,
               const float* __restrict__ W2, const float* __restrict__ b2,
               float* __restrict__ out)
{
    extern __shared__ unsigned char smem_raw[];
    SmemT* s = reinterpret_cast<SmemT*>(smem_raw);

    const int t   = threadIdx.x;
    const int w   = t >> 5;
    const int l   = t & 31;
    const int og  = w & 3;           // warp's output group: o in [og*8, og*8+8)
    const int og8 = og * 8;
    const int eh  = w >> 2;          // edge half (0/1): warp covers 64 edges
    const int ebase = eh * 64 + l * 2;   // thread's 2 consecutive edges
    const int e0  = blockIdx.x * TE;

    // ---------------- staging: e_vw (transposed), hw gather, b2 dup, b0 ----
    for (int idx = t; idx < TE * ES; idx += NTHR) {
        int e = idx >> 4, k = idx & 15;
        int ge = e0 + e;
        s->eT[k][e] = (ge < E_TOT) ? e_vw[ge * ES + k] : 0.f;
    }
    for (int idx = t; idx < INS * TE; idx += NTHR) {
        int i = idx >> 7;
        int e = idx & (TE - 1);
        int ge = e0 + e;
        float v = 0.f;
        if (ge < E_TOT) {
            int b  = ge / NBR;
            int r  = ge - b * NBR;
            int ii = (r * INS + i) / NBR;   // faithful expand/view gather
            v = h_w[b * INS + ii];
        }
        s->hwT[i][e] = v;
    }
    for (int idx = t; idx < INS * OUTS; idx += NTHR) {
        int i = idx >> 5, o = idx & 31;
        float v = b2[o * INS + i];
        s->b2d[i][o] = make_float2(v, v);
    }
    if (t < HID) s->sbias[t] = b0[t];
    __syncthreads();

    // ---------------- layer 0: x1 = relu(e @ W0^T + b0), K = 16 ----------
    const int o_st  = t & 31;        // staging: lane -> output row
    const int kb_st = t >> 5;        // staging: warp -> k block
    for (int hc = 0; hc < 4; ++hc) {
        {
            const float* src = W0 + (hc * 32 + o_st) * ES + kb_st * 2;
            float2 v = *reinterpret_cast<const float2*>(src);
            s->wdA[kb_st * 2 + 0][o_st] = make_float2(v.x, v.x);
            s->wdA[kb_st * 2 + 1][o_st] = make_float2(v.y, v.y);
        }
        __syncthreads();
        ull acc[8];
        #pragma unroll
        for (int q = 0; q < 8; ++q) acc[q] = 0ull;
        #pragma unroll
        for (int k = 0; k < ES; ++k) {
            ull a = *reinterpret_cast<const ull*>(&s->eT[k][ebase]);
            const ulonglong2* bp = reinterpret_cast<const ulonglong2*>(&s->wdA[k][og8]);
            ulonglong2 b01 = bp[0], b23 = bp[1], b45 = bp[2], b67 = bp[3];
            fma2(acc[0], a, b01.x); fma2(acc[1], a, b01.y);
            fma2(acc[2], a, b23.x); fma2(acc[3], a, b23.y);
            fma2(acc[4], a, b45.x); fma2(acc[5], a, b45.y);
            fma2(acc[6], a, b67.x); fma2(acc[7], a, b67.y);
        }
        #pragma unroll
        for (int q = 0; q < 8; ++q) {
            int h = hc * 32 + og8 + q;
            float x, y; upk2(acc[q], x, y);
            float bb = s->sbias[h];
            x = fmaxf(x + bb, 0.f); y = fmaxf(y + bb, 0.f);
            *reinterpret_cast<float2*>(&s->u.x1T[h][ebase]) = make_float2(x, y);
        }
        __syncthreads();
    }

    if (t < HID) s->sbias[t] = b1[t];
    __syncthreads();

    // ---------------- layer 1: x2 = relu(x1 @ W1^T + b1), K = 128 --------
    for (int hc = 0; hc < 4; ++hc) {
        {
            const float* src = W1 + (hc * 32 + o_st) * HID + kb_st * 16;
            #pragma unroll
            for (int m = 0; m < 4; ++m) {
                float4 v = *reinterpret_cast<const float4*>(src + m * 4);
                int k = kb_st * 16 + m * 4;
                s->wdA[k + 0][o_st] = make_float2(v.x, v.x);
                s->wdA[k + 1][o_st] = make_float2(v.y, v.y);
                s->wdA[k + 2][o_st] = make_float2(v.z, v.z);
                s->wdA[k + 3][o_st] = make_float2(v.w, v.w);
            }
        }
        __syncthreads();
        ull acc[8];
        #pragma unroll
        for (int q = 0; q < 8; ++q) acc[q] = 0ull;
        #pragma unroll 8
        for (int k = 0; k < HID; ++k) {
            ull a = *reinterpret_cast<const ull*>(&s->u.x1T[k][ebase]);
            const ulonglong2* bp = reinterpret_cast<const ulonglong2*>(&s->wdA[k][og8]);
            ulonglong2 b01 = bp[0], b23 = bp[1], b45 = bp[2], b67 = bp[3];
            fma2(acc[0], a, b01.x); fma2(acc[1], a, b01.y);
            fma2(acc[2], a, b23.x); fma2(acc[3], a, b23.y);
            fma2(acc[4], a, b45.x); fma2(acc[5], a, b45.y);
            fma2(acc[6], a, b67.x); fma2(acc[7], a, b67.y);
        }
        #pragma unroll
        for (int q = 0; q < 8; ++q) {
            int h = hc * 32 + og8 + q;
            float x, y; upk2(acc[q], x, y);
            float bb = s->sbias[h];
            x = fmaxf(x + bb, 0.f); y = fmaxf(y + bb, 0.f);
            *reinterpret_cast<float2*>(&s->x2T[h][ebase]) = make_float2(x, y);
        }
        __syncthreads();
    }

    // ---------------- layer 2 + hw contraction -----------------------------
    // out[e,o] = sum_i hw[e,i] * ( b2[o*32+i] + sum_j x2[e,j]*W2[o*32+i, j] )
    ull acc[8];
    #pragma unroll
    for (int q = 0; q < 8; ++q) acc[q] = 0ull;

    // bias term: sum_i hw[e,i] * b2[o*32+i]
    #pragma unroll
    for (int i = 0; i < INS; ++i) {
        ull hw2 = *reinterpret_cast<const ull*>(&s->hwT[i][ebase]);
        const ulonglong2* bp = reinterpret_cast<const ulonglong2*>(&s->b2d[i][og8]);
        ulonglong2 b01 = bp[0], b23 = bp[1], b45 = bp[2], b67 = bp[3];
        fma2(acc[0], hw2, b01.x); fma2(acc[1], hw2, b01.y);
        fma2(acc[2], hw2, b23.x); fma2(acc[3], hw2, b23.y);
        fma2(acc[4], hw2, b45.x); fma2(acc[5], hw2, b45.y);
        fma2(acc[6], hw2, b67.x); fma2(acc[7], hw2, b67.y);
    }

    // W2 slice for i: rows (o*32 + i), K = 128.  Double-buffered staging with
    // LDG prefetch hoisted ahead of compute (hides L2 latency).
    const float* w2base = W2 + o_st * (INS * HID) + kb_st * 16;
    {
        const float* p = w2base;                       // i = 0
        #pragma unroll
        for (int m = 0; m < 4; ++m) {
            float4 v = *reinterpret_cast<const float4*>(p + m * 4);
            int k = kb_st * 16 + m * 4;
            s->wdA[k + 0][o_st] = make_float2(v.x, v.x);
            s->wdA[k + 1][o_st] = make_float2(v.y, v.y);
            s->wdA[k + 2][o_st] = make_float2(v.z, v.z);
            s->wdA[k + 3][o_st] = make_float2(v.w, v.w);
        }
    }
    __syncthreads();

    float2 (*wdc)[OUTS] = s->wdA;      // current
    float2 (*wdn)[OUTS] = s->u.wdB;    // next (aliases dead x1T)

    for (int i = 0; i < INS; ++i) {
        float4 n0, n1, n2, n3;
        const bool more = (i + 1 < INS);
        if (more) {
            const float* p = w2base + (i + 1) * HID;
            n0 = *reinterpret_cast<const float4*>(p + 0);
            n1 = *reinterpret_cast<const float4*>(p + 4);
            n2 = *reinterpret_cast<const float4*>(p + 8);
            n3 = *reinterpret_cast<const float4*>(p + 12);
        }

        ull hw2 = *reinterpret_cast<const ull*>(&s->hwT[i][ebase]);
        #pragma unroll 8
        for (int j = 0; j < HID; ++j) {
            ull a  = *reinterpret_cast<const ull*>(&s->x2T[j][ebase]);
            ull tj = mul2(a, hw2);
            const ulonglong2* bp = reinterpret_cast<const ulonglong2*>(&wdc[j][og8]);
            ulonglong2 b01 = bp[0], b23 = bp[1], b45 = bp[2], b67 = bp[3];
            fma2(acc[0], tj, b01.x); fma2(acc[1], tj, b01.y);
            fma2(acc[2], tj, b23.x); fma2(acc[3], tj, b23.y);
            fma2(acc[4], tj, b45.x); fma2(acc[5], tj, b45.y);
            fma2(acc[6], tj, b67.x); fma2(acc[7], tj, b67.y);
        }

        if (more) {
            int k = kb_st * 16;
            wdn[k +  0][o_st] = make_float2(n0.x, n0.x);
            wdn[k +  1][o_st] = make_float2(n0.y, n0.y);
            wdn[k +  2][o_st] = make_float2(n0.z, n0.z);
            wdn[k +  3][o_st] = make_float2(n0.w, n0.w);
            wdn[k +  4][o_st] = make_float2(n1.x, n1.x);
            wdn[k +  5][o_st] = make_float2(n1.y, n1.y);
            wdn[k +  6][o_st] = make_float2(n1.z, n1.z);
            wdn[k +  7][o_st] = make_float2(n1.w, n1.w);
            wdn[k +  8][o_st] = make_float2(n2.x, n2.x);
            wdn[k +  9][o_st] = make_float2(n2.y, n2.y);
            wdn[k + 10][o_st] = make_float2(n2.z, n2.z);
            wdn[k + 11][o_st] = make_float2(n2.w, n2.w);
            wdn[k + 12][o_st] = make_float2(n3.x, n3.x);
            wdn[k + 13][o_st] = make_float2(n3.y, n3.y);
            wdn[k + 14][o_st] = make_float2(n3.z, n3.z);
            wdn[k + 15][o_st] = make_float2(n3.w, n3.w);
        }
        __syncthreads();
        float2 (*tmp)[OUTS] = wdc; wdc = wdn; wdn = tmp;
    }

    // ---------------- output: out[e, og8..og8+7], 2 edges per thread ------
    #pragma unroll
    for (int ei = 0; ei < 2; ++ei) {
        int ge = e0 + ebase + ei;
        if (ge < E_TOT) {
            float v[8];
            #pragma unroll
            for (int q = 0; q < 8; ++q) {
                float x, y; upk2(acc[q], x, y);
                v[q] = ei ? y : x;
            }
            float4* dst = reinterpret_cast<float4*>(out + ge * OUTS + og8);
            dst[0] = make_float4(v[0], v[1], v[2], v[3]);
            dst[1] = make_float4(v[4], v[5], v[6], v[7]);
        }
    }
}

extern "C" void kernel_launch(void* const* d_in, const int* in_sizes, int n_in,
                              void* d_out, int out_size)
{
    // metadata order: h_v, h_w, e_vw, W0, b0, W1, b1, W2, b2   (h_v unused)
    const float* h_w  = (const float*)d_in[1];
    const float* e_vw = (const float*)d_in[2];
    const float* W0   = (const float*)d_in[3];
    const float* b0   = (const float*)d_in[4];
    const float* W1   = (const float*)d_in[5];
    const float* b1   = (const float*)d_in[6];
    const float* W2   = (const float*)d_in[7];
    const float* b2   = (const float*)d_in[8];
    float* out = (float*)d_out;

    int smem = (int)sizeof(SmemT);
    cudaFuncSetAttribute(msgfunc_kernel,
                         cudaFuncAttributeMaxDynamicSharedMemorySize, smem);
    int grid = (E_TOT + TE - 1) / TE;
    msgfunc_kernel<<<grid, NTHR, smem>>>(h_w, e_vw, W0, b0, W1, b1, W2, b2, out);
}

// round 3
// speedup vs baseline: 5.7252x; 5.7252x over previous
#include <cuda_runtime.h>
typedef unsigned long long ull;

#define E_TOT 200000
#define NBR 20
#define AP 128          // activation/weight row pitch (floats)
#define TP 256          // Tt row pitch

__device__ float gTt[128 * 256];   // T transposed: gTt[j*256 + o*8 + m]
__device__ float gTb[256];         // gTb[m*32 + o]

__global__ void prep_kernel(const float* __restrict__ W2, const float* __restrict__ b2)
{
    int o = blockIdx.x, j = threadIdx.x;   // 32 blocks x 128 threads
    float run = 0.f;
    #pragma unroll
    for (int i = 0; i < 32; ++i) {
        run += W2[(o * 32 + i) * 128 + j];
        if ((i & 3) == 3) gTt[j * 256 + o * 8 + (i >> 2)] = run;
    }
    if (j < 8) {
        float sb = 0.f;
        for (int i = 0; i < 4 * (j + 1); ++i) sb += b2[o * 32 + i];
        gTb[j * 32 + o] = sb;
    }
}

struct Smem {
    union {
        struct { float w1t[128][AP]; float x1f[128][AP]; } p;  // x1f doubles as W1 tmp
        float Tt[128][TP];
    } big;
    float x2f[128][AP];
    float ep[16][AP];
    float w0t[16][AP];
    float b0s[128], b1s[128], Tbs[256];
    float cA[128], cB[128], c7[128];
    int   mAi[128], mBi[128];
};

__device__ __forceinline__ ull dup2(float x) {
    ull r; asm("mov.b64 %0, {%1, %1};" : "=l"(r) : "f"(x)); return r;
}
__device__ __forceinline__ void fma2(ull& d, ull a, ull b) {
    asm("fma.rn.f32x2 %0, %1, %2, %0;" : "+l"(d) : "l"(a), "l"(b));
}
__device__ __forceinline__ void upk2(ull v, float& lo, float& hi) {
    asm("mov.b64 {%0, %1}, %2;" : "=f"(lo), "=f"(hi) : "l"(v));
}

// N=128-output GEMM tile: warp w owns h in [16w,16w+16) as 8 packed pairs,
// lane owns 4 edges. Weights read pre-packed (ull), x broadcast-dup'd.
template <int K>
__device__ __forceinline__ void gemm_relu(const float (*xin)[AP], const float (*wt)[AP],
                                          const float* bias, float (*xout)[AP],
                                          int w, int lane)
{
    ull acc[8][4];
    #pragma unroll
    for (int hp = 0; hp < 8; ++hp)
        #pragma unroll
        for (int e = 0; e < 4; ++e) acc[hp][e] = 0ull;

    for (int j = 0; j < K; ++j) {
        float4 xv = *(const float4*)&xin[j][4 * lane];
        const ulonglong2* wp = (const ulonglong2*)&wt[j][16 * w];
        ull wv[8];
        #pragma unroll
        for (int q = 0; q < 4; ++q) { ulonglong2 u = wp[q]; wv[2*q] = u.x; wv[2*q+1] = u.y; }
        ull xd[4] = { dup2(xv.x), dup2(xv.y), dup2(xv.z), dup2(xv.w) };
        #pragma unroll
        for (int hp = 0; hp < 8; ++hp)
            #pragma unroll
            for (int e = 0; e < 4; ++e) fma2(acc[hp][e], wv[hp], xd[e]);
    }
    #pragma unroll
    for (int hp = 0; hp < 8; ++hp) {
        int h = 16 * w + 2 * hp;
        float be = bias[h], bo = bias[h + 1];
        float ve[4], vo[4];
        #pragma unroll
        for (int e = 0; e < 4; ++e) {
            float x, y; upk2(acc[hp][e], x, y);
            ve[e] = fmaxf(x + be, 0.f); vo[e] = fmaxf(y + bo, 0.f);
        }
        *(float4*)&xout[h][4 * lane]     = make_float4(ve[0], ve[1], ve[2], ve[3]);
        *(float4*)&xout[h + 1][4 * lane] = make_float4(vo[0], vo[1], vo[2], vo[3]);
    }
}

__global__ void __launch_bounds__(256, 1)
msg_kernel(const float* __restrict__ h_w, const float* __restrict__ e_vw,
           const float* __restrict__ W0, const float* __restrict__ b0,
           const float* __restrict__ W1, const float* __restrict__ b1,
           float* __restrict__ out)
{
    extern __shared__ unsigned char sraw[];
    Smem* s = (Smem*)sraw;
    const int t = threadIdx.x, w = t >> 5, lane = t & 31;
    const int e0 = blockIdx.x * 128;

    // ---- stage e_vw transposed -> ep[j][e] ----
    {
        int e = t >> 1, hf = (t & 1) * 8, ge = e0 + e;
        float v[8] = {0,0,0,0,0,0,0,0};
        if (ge < E_TOT) {
            float4 a = *(const float4*)(e_vw + (size_t)ge * 16 + hf);
            float4 b = *(const float4*)(e_vw + (size_t)ge * 16 + hf + 4);
            v[0]=a.x; v[1]=a.y; v[2]=a.z; v[3]=a.w; v[4]=b.x; v[5]=b.y; v[6]=b.z; v[7]=b.w;
        }
        #pragma unroll
        for (int jj = 0; jj < 8; ++jj) s->ep[hf + jj][e] = v[jj];
    }
    // ---- stage W1 coalesced into tmp (= x1f region) ----
    #pragma unroll
    for (int k = 0; k < 16; ++k) {
        int idx = t + k * 256, n = idx >> 5, c4 = idx & 31;
        float4 v = *(const float4*)(W1 + n * 128 + c4 * 4);
        *(float4*)&s->big.p.x1f[n][c4 * 4] = v;
    }
    // ---- biases, Tb, per-edge telescoping coefficients ----
    s->Tbs[t] = gTb[t];
    if (t < 128) {
        s->b0s[t] = b0[t]; s->b1s[t] = b1[t];
        int ge = e0 + t;
        float ca = 0.f, cb = 0.f, c7v = 0.f; int ma = 0, mb = 0;
        if (ge < E_TOT) {
            int bb = ge / NBR, r = ge - bb * NBR;
            int rm = (r * 32) % NBR;
            int i1 = (rm == 0) ? 20 : 20 - rm;
            int v0 = (r * 32) / NBR;
            float h0 = h_w[bb * 32 + v0], h1 = h_w[bb * 32 + v0 + 1];
            ca = h0 - h1; ma = (i1 >> 2) - 1;
            if (i1 + 20 < 32) {
                float h2 = h_w[bb * 32 + v0 + 2];
                cb = h1 - h2; mb = ((i1 + 20) >> 2) - 1; c7v = h2;
            } else c7v = h1;
        }
        s->cA[t] = ca; s->cB[t] = cb; s->c7[t] = c7v; s->mAi[t] = ma; s->mBi[t] = mb;
    }
    __syncthreads();

    // ---- transpose tmp -> w1t (scalar reads j=lane-varying: conflict-free;
    //      float4 writes: contiguous within phase) ----
    #pragma unroll
    for (int m = 0; m < 16; ++m) {
        int idx = t + m * 256, j = idx & 127, n0 = (idx >> 7) * 4;
        float a0 = s->big.p.x1f[n0][j],     a1 = s->big.p.x1f[n0 + 1][j];
        float a2 = s->big.p.x1f[n0 + 2][j], a3 = s->big.p.x1f[n0 + 3][j];
        *(float4*)&s->big.p.w1t[j][n0] = make_float4(a0, a1, a2, a3);
    }
    // ---- W0 transpose direct from gmem ----
    if (t < 128) {
        float v[16];
        #pragma unroll
        for (int q = 0; q < 4; ++q) {
            float4 a = *(const float4*)(W0 + t * 16 + q * 4);
            v[4*q]=a.x; v[4*q+1]=a.y; v[4*q+2]=a.z; v[4*q+3]=a.w;
        }
        #pragma unroll
        for (int j = 0; j < 16; ++j) s->w0t[j][t] = v[j];
    }
    __syncthreads();

    gemm_relu<16>(s->ep, s->w0t, s->b0s, s->big.p.x1f, w, lane);
    __syncthreads();
    gemm_relu<128>(s->big.p.x1f, s->big.p.w1t, s->b1s, s->x2f, w, lane);
    __syncthreads();

    // ---- stage Tt (overwrites w1t/x1f) ----
    #pragma unroll
    for (int k = 0; k < 32; ++k) {
        int idx = t + k * 256, j = idx >> 6, c4 = idx & 63;
        float4 v = *(const float4*)(gTt + j * 256 + c4 * 4);
        *(float4*)&s->big.Tt[j][c4 * 4] = v;
    }
    __syncthreads();

    // ---- GEMM_D: D = x2 @ T^T.  warp w owns n' in [32w,32w+32) (o=4w+..,
    //      all 8 m per o -> epilogue thread-local). lane owns 4 edges. ----
    ull acc[16][4];
    #pragma unroll
    for (int np = 0; np < 16; ++np)
        #pragma unroll
        for (int e = 0; e < 4; ++e) acc[np][e] = 0ull;

    for (int j = 0; j < 128; ++j) {
        float4 xv = *(const float4*)&s->x2f[j][4 * lane];
        const ulonglong2* tp = (const ulonglong2*)&s->big.Tt[j][32 * w];
        ull tv[16];
        #pragma unroll
        for (int q = 0; q < 8; ++q) { ulonglong2 u = tp[q]; tv[2*q] = u.x; tv[2*q+1] = u.y; }
        ull xd[4] = { dup2(xv.x), dup2(xv.y), dup2(xv.z), dup2(xv.w) };
        #pragma unroll
        for (int np = 0; np < 16; ++np)
            #pragma unroll
            for (int e = 0; e < 4; ++e) fma2(acc[np][e], tv[np], xd[e]);
    }

    // ---- epilogue: out[e,o] = cA(D[mA]+Tb) + cB(D[mB]+Tb) + c7(D[7]+Tb) ----
    #pragma unroll
    for (int e = 0; e < 4; ++e) {
        int el = 4 * lane + e, ge = e0 + el;
        if (ge >= E_TOT) continue;
        float D[4][8];
        #pragma unroll
        for (int np = 0; np < 16; ++np) {
            float x, y; upk2(acc[np][e], x, y);
            int n2 = 2 * np;
            D[n2 >> 3][n2 & 7] = x; D[(n2+1) >> 3][(n2+1) & 7] = y;
        }
        float ca = s->cA[el], cb = s->cB[el], c7v = s->c7[el];
        int ma = s->mAi[el], mb = s->mBi[el];
        float r[4];
        #pragma unroll
        for (int o = 0; o < 4; ++o) {
            int O = 4 * w + o;
            r[o] = ca * (D[o][ma] + s->Tbs[ma * 32 + O])
                 + cb * (D[o][mb] + s->Tbs[mb * 32 + O])
                 + c7v * (D[o][7] + s->Tbs[224 + O]);
        }
        *(float4*)(out + (size_t)ge * 32 + 4 * w) = make_float4(r[0], r[1], r[2], r[3]);
    }
}

extern "C" void kernel_launch(void* const* d_in, const int* in_sizes, int n_in,
                              void* d_out, int out_size)
{
    const float* h_w  = (const float*)d_in[1];
    const float* e_vw = (const float*)d_in[2];
    const float* W0   = (const float*)d_in[3];
    const float* b0   = (const float*)d_in[4];
    const float* W1   = (const float*)d_in[5];
    const float* b1   = (const float*)d_in[6];
    const float* W2   = (const float*)d_in[7];
    const float* b2   = (const float*)d_in[8];
    float* out = (float*)d_out;

    prep_kernel<<<32, 128>>>(W2, b2);

    int smem = (int)sizeof(Smem);
    cudaFuncSetAttribute(msg_kernel, cudaFuncAttributeMaxDynamicSharedMemorySize, smem);
    msg_kernel<<<(E_TOT + 127) / 128, 256, smem>>>(h_w, e_vw, W0, b0, W1, b1, out);
}

// round 5
// speedup vs baseline: 16.4543x; 2.8740x over previous
#include <cuda_runtime.h>
#include <cuda_bf16.h>
#include <cstdint>

typedef unsigned int u32;

#define E_TOT   200000
#define N_TILES 1563
#define GRID    148

#define OFF_W0H 0
#define OFF_W0L 4096
#define OFF_W1H 8192
#define OFF_W1L 40960
#define OFF_TH  73728
#define OFF_TL  139264
#define OFF_TB  204800
#define OFF_B0  205824
#define OFF_B1  206336
#define SMEM_BYTES 206848

__device__ uint4 gWimg[SMEM_BYTES / 16];

// XOR-swizzled byte offset within a 256B-row bf16 image: row n, col k (0..127)
__host__ __device__ __forceinline__ u32 sw_off(int n, int k) {
    int chunk = k >> 3;
    return (u32)(n * 256 + (((chunk ^ (n & 7)) << 4) | ((k & 7) << 1)));
}

// ---------------------------------------------------------------------------
// prep kernels: build split-bf16 weight image (exact smem layout) + Tb + biases
// ---------------------------------------------------------------------------
__device__ __forceinline__ void put_hl(u32 offh, u32 offl, u32 boff, float v) {
    char* img = (char*)gWimg;
    __nv_bfloat16 h = __float2bfloat16(v);
    __nv_bfloat16 l = __float2bfloat16(v - __bfloat162float(h));
    *(__nv_bfloat16*)(img + offh + boff) = h;
    *(__nv_bfloat16*)(img + offl + boff) = l;
}

__global__ void prep_w(const float* __restrict__ W0, const float* __restrict__ W1,
                       const float* __restrict__ b0, const float* __restrict__ b1)
{
    int id = blockIdx.x * 256 + threadIdx.x;
    if (id < 2048) {                       // W0 [128n][16k], 32B rows, no swizzle
        int n = id >> 4, k = id & 15;
        put_hl(OFF_W0H, OFF_W0L, (u32)(n * 32 + k * 2), W0[id]);
    } else if (id < 2048 + 16384) {        // W1 [128n][128k], swizzled
        int j = id - 2048;
        put_hl(OFF_W1H, OFF_W1L, sw_off(j >> 7, j & 127), W1[j]);
    }
    if (id < 128) {
        *(float*)((char*)gWimg + OFF_B0 + id * 4) = b0[id];
        *(float*)((char*)gWimg + OFF_B1 + id * 4) = b1[id];
    }
}

__global__ void prep_T(const float* __restrict__ W2, const float* __restrict__ b2)
{
    int o = blockIdx.x, j = threadIdx.x;   // 32 x 128
    float run = 0.f;
    #pragma unroll
    for (int i = 0; i < 32; ++i) {
        run += W2[(o * 32 + i) * 128 + j];
        if ((i & 3) == 3) put_hl(OFF_TH, OFF_TL, sw_off(o * 8 + (i >> 2), j), run);
    }
    if (j < 8) {
        float sb = 0.f;
        for (int i = 0; i < 4 * (j + 1); ++i) sb += b2[o * 32 + i];
        *(float*)((char*)gWimg + OFF_TB + (o * 8 + j) * 4) = sb;
    }
}

// ---------------------------------------------------------------------------
__device__ __forceinline__ u32 smem_u32(const void* p) {
    u32 a;
    asm("{ .reg .u64 t; cvta.to.shared.u64 t, %1; cvt.u32.u64 %0, t; }" : "=r"(a) : "l"(p));
    return a;
}
__device__ __forceinline__ void ldsm4(u32* r, u32 a) {
    asm volatile("ldmatrix.sync.aligned.m8n8.x4.shared.b16 {%0,%1,%2,%3}, [%4];"
        : "=r"(r[0]), "=r"(r[1]), "=r"(r[2]), "=r"(r[3]) : "r"(a));
}
__device__ __forceinline__ void mma(float* d, const u32* a, const u32* b) {
    asm volatile("mma.sync.aligned.m16n8k16.row.col.f32.bf16.bf16.f32 "
        "{%0,%1,%2,%3}, {%4,%5,%6,%7}, {%8,%9}, {%0,%1,%2,%3};"
        : "+f"(d[0]), "+f"(d[1]), "+f"(d[2]), "+f"(d[3])
        : "r"(a[0]), "r"(a[1]), "r"(a[2]), "r"(a[3]), "r"(b[0]), "r"(b[1]));
}
// pack two f32 into bf16x2 (lo=f0, hi=f1), return lo-residual pack too
__device__ __forceinline__ u32 packhl(float f0, float f1, u32& lo) {
    u32 h;
    asm("cvt.rn.bf16x2.f32 %0, %1, %2;" : "=r"(h) : "f"(f1), "f"(f0));
    float h0 = __uint_as_float(h << 16);
    float h1 = __uint_as_float(h & 0xffff0000u);
    asm("cvt.rn.bf16x2.f32 %0, %1, %2;" : "=r"(lo) : "f"(f1 - h1), "f"(f0 - h0));
    return h;
}
__device__ __forceinline__ float relu(float x) { return fmaxf(x, 0.f); }

__device__ __forceinline__ void eparams(const float* __restrict__ h_w, int ge,
                                        float& cA, int& mA, float& cB, int& mB, float& c7)
{
    cA = cB = c7 = 0.f; mA = 0; mB = 5;
    if (ge < E_TOT) {
        int bb = ge / 20, r20 = ge - bb * 20;
        int rm = (r20 * 32) % 20;
        int i1 = (rm == 0) ? 20 : 20 - rm;
        int v0 = (r20 * 32) / 20;
        float h0 = h_w[bb * 32 + v0], h1 = h_w[bb * 32 + v0 + 1];
        cA = h0 - h1; mA = (i1 >> 2) - 1;
        if (i1 + 20 < 32) {
            float h2 = h_w[bb * 32 + v0 + 2];
            cB = h1 - h2; mB = ((i1 + 20) >> 2) - 1; c7 = h2;
        } else c7 = h1;
    }
}
__device__ __forceinline__ float wcoef(int m, float cA, int mA, float cB, int mB, float c7) {
    float r = 0.f;
    if (m == mA) r += cA;
    if (m == mB) r += cB;
    if (m == 7)  r += c7;
    return r;
}

__global__ void __launch_bounds__(256, 1)
msg_kernel(const float* __restrict__ h_w, const float* __restrict__ e_vw,
           float* __restrict__ out)
{
    extern __shared__ unsigned char sraw[];
    const int t = threadIdx.x, w = t >> 5, lane = t & 31;
    const int lr = lane & 7, g = lane >> 3, q = lane & 3;
    const int kc = 2 * q;

    // stage weight image (202KB, uint4 bulk copy; layouts identical)
    {
        uint4* dst = (uint4*)sraw;
        for (int i = t; i < SMEM_BYTES / 16; i += 256) dst[i] = gWimg[i];
    }
    __syncthreads();

    const u32 sb = smem_u32(sraw);
    const float* b0s = (const float*)(sraw + OFF_B0);
    const float* b1s = (const float*)(sraw + OFF_B1);
    const float* Tbs = (const float*)(sraw + OFF_TB);

    for (int tile = blockIdx.x; tile < N_TILES; tile += GRID) {
        const int e0w = tile * 128 + w * 16;
        const int ge0 = e0w + (lane >> 2);
        const int ge1 = ge0 + 8;

        // ---- e fragments (A of GEMM0), hi/lo split ----
        float e00 = 0, e01 = 0, e02 = 0, e03 = 0;
        float e10 = 0, e11 = 0, e12 = 0, e13 = 0;
        if (ge0 < E_TOT) {
            float2 u = *(const float2*)(e_vw + (size_t)ge0 * 16 + kc);
            float2 v = *(const float2*)(e_vw + (size_t)ge0 * 16 + kc + 8);
            e00 = u.x; e01 = u.y; e02 = v.x; e03 = v.y;
        }
        if (ge1 < E_TOT) {
            float2 u = *(const float2*)(e_vw + (size_t)ge1 * 16 + kc);
            float2 v = *(const float2*)(e_vw + (size_t)ge1 * 16 + kc + 8);
            e10 = u.x; e11 = u.y; e12 = v.x; e13 = v.y;
        }
        u32 ah[4], al[4];
        ah[0] = packhl(e00, e01, al[0]);
        ah[1] = packhl(e10, e11, al[1]);
        ah[2] = packhl(e02, e03, al[2]);
        ah[3] = packhl(e12, e13, al[3]);

        // ---- GEMM0: x1acc = e @ W0^T (K=16), 3 split products ----
        float acc[64];
        #pragma unroll
        for (int i = 0; i < 64; ++i) acc[i] = 0.f;
        #pragma unroll
        for (int ntp = 0; ntp < 8; ++ntp) {
            int n = (2 * ntp + (g >> 1)) * 8 + lr;
            u32 ad = sb + OFF_W0H + n * 32 + (g & 1) * 16;
            u32 bh[4], bl[4];
            ldsm4(bh, ad);
            ldsm4(bl, ad + (OFF_W0L - OFF_W0H));
            mma(acc + 8 * ntp,     ah, bh);
            mma(acc + 8 * ntp,     ah, bl);
            mma(acc + 8 * ntp,     al, bh);
            mma(acc + 8 * ntp + 4, ah, bh + 2);
            mma(acc + 8 * ntp + 4, ah, bl + 2);
            mma(acc + 8 * ntp + 4, al, bh + 2);
        }

        // ---- bias + relu -> x1 A-fragments (in-register layout chaining) ----
        u32 x1h[8][4], x1l[8][4];
        #pragma unroll
        for (int s = 0; s < 8; ++s) {
            int n0 = 16 * s + kc;
            float bb00 = b0s[n0], bb01 = b0s[n0 + 1], bb10 = b0s[n0 + 8], bb11 = b0s[n0 + 9];
            const float* A = acc + 8 * s;
            x1h[s][0] = packhl(relu(A[0] + bb00), relu(A[1] + bb01), x1l[s][0]);
            x1h[s][1] = packhl(relu(A[2] + bb00), relu(A[3] + bb01), x1l[s][1]);
            x1h[s][2] = packhl(relu(A[4] + bb10), relu(A[5] + bb11), x1l[s][2]);
            x1h[s][3] = packhl(relu(A[6] + bb10), relu(A[7] + bb11), x1l[s][3]);
        }

        // ---- GEMM1: x2acc = x1 @ W1^T (K=128) ----
        #pragma unroll
        for (int i = 0; i < 64; ++i) acc[i] = 0.f;
        #pragma unroll
        for (int ntp = 0; ntp < 8; ++ntp) {
            int n = (2 * ntp + (g >> 1)) * 8 + lr;
            u32 rb = sb + OFF_W1H + n * 256;
            u32 sx = (u32)(n & 7) << 4;
            #pragma unroll
            for (int s = 0; s < 8; ++s) {
                u32 ad = rb + (((u32)(2 * s + (g & 1)) << 4) ^ sx);
                u32 bh[4], bl[4];
                ldsm4(bh, ad);
                ldsm4(bl, ad + (OFF_W1L - OFF_W1H));
                mma(acc + 8 * ntp,     x1h[s], bh);
                mma(acc + 8 * ntp,     x1h[s], bl);
                mma(acc + 8 * ntp,     x1l[s], bh);
                mma(acc + 8 * ntp + 4, x1h[s], bh + 2);
                mma(acc + 8 * ntp + 4, x1h[s], bl + 2);
                mma(acc + 8 * ntp + 4, x1l[s], bh + 2);
            }
        }

        // ---- bias + relu -> x2 fragments ----
        u32 x2h[8][4], x2l[8][4];
        #pragma unroll
        for (int s = 0; s < 8; ++s) {
            int n0 = 16 * s + kc;
            float bb00 = b1s[n0], bb01 = b1s[n0 + 1], bb10 = b1s[n0 + 8], bb11 = b1s[n0 + 9];
            const float* A = acc + 8 * s;
            x2h[s][0] = packhl(relu(A[0] + bb00), relu(A[1] + bb01), x2l[s][0]);
            x2h[s][1] = packhl(relu(A[2] + bb00), relu(A[3] + bb01), x2l[s][1]);
            x2h[s][2] = packhl(relu(A[4] + bb10), relu(A[5] + bb11), x2l[s][2]);
            x2h[s][3] = packhl(relu(A[6] + bb10), relu(A[7] + bb11), x2l[s][3]);
        }

        // ---- telescoping coefficients; thread covers msegs kc, kc+1 ----
        float cA0, cB0, c70, cA1, cB1, c71; int mA0, mB0, mA1, mB1;
        eparams(h_w, ge0, cA0, mA0, cB0, mB0, c70);
        eparams(h_w, ge1, cA1, mA1, cB1, mB1, c71);
        float w00 = wcoef(kc,     cA0, mA0, cB0, mB0, c70);
        float w01 = wcoef(kc + 1, cA0, mA0, cB0, mB0, c70);
        float w10 = wcoef(kc,     cA1, mA1, cB1, mB1, c71);
        float w11 = wcoef(kc + 1, cA1, mA1, cB1, mB1, c71);

        // ---- GEMM_D + epilogue, N=256 in 4 chunks (o-groups of 8) ----
        for (int cn = 0; cn < 4; ++cn) {
            float accd[32];
            #pragma unroll
            for (int i = 0; i < 32; ++i) accd[i] = 0.f;
            #pragma unroll
            for (int ntp = 0; ntp < 4; ++ntp) {
                int n = (cn * 8 + 2 * ntp + (g >> 1)) * 8 + lr;
                u32 rb = sb + OFF_TH + n * 256;
                u32 sx = (u32)(n & 7) << 4;
                #pragma unroll
                for (int s = 0; s < 8; ++s) {
                    u32 ad = rb + (((u32)(2 * s + (g & 1)) << 4) ^ sx);
                    u32 bh[4], bl[4];
                    ldsm4(bh, ad);
                    ldsm4(bl, ad + (OFF_TL - OFF_TH));
                    mma(accd + 8 * ntp,     x2h[s], bh);
                    mma(accd + 8 * ntp,     x2h[s], bl);
                    mma(accd + 8 * ntp,     x2l[s], bh);
                    mma(accd + 8 * ntp + 4, x2h[s], bh + 2);
                    mma(accd + 8 * ntp + 4, x2h[s], bl + 2);
                    mma(accd + 8 * ntp + 4, x2l[s], bh + 2);
                }
            }
            // epilogue: out[e,o] = sum_m w_m * (D[o*8+m] + Tb[o*8+m]); quad butterfly
            float v00 = 0.f, v01 = 0.f, v10 = 0.f, v11 = 0.f;
            #pragma unroll
            for (int nt = 0; nt < 8; ++nt) {
                int o8 = cn * 64 + nt * 8;
                float tb0 = Tbs[o8 + kc], tb1 = Tbs[o8 + kc + 1];
                const float* A = accd + 4 * nt;
                float s0 = w00 * (A[0] + tb0) + w01 * (A[1] + tb1);
                float s1 = w10 * (A[2] + tb0) + w11 * (A[3] + tb1);
                s0 += __shfl_xor_sync(0xffffffffu, s0, 1);
                s0 += __shfl_xor_sync(0xffffffffu, s0, 2);
                s1 += __shfl_xor_sync(0xffffffffu, s1, 1);
                s1 += __shfl_xor_sync(0xffffffffu, s1, 2);
                if (q == (nt >> 1)) {
                    if (nt & 1) { v01 = s0; v11 = s1; }
                    else        { v00 = s0; v10 = s1; }
                }
            }
            int oc = cn * 8 + 2 * q;
            if (ge0 < E_TOT)
                *(float2*)(out + (size_t)ge0 * 32 + oc) = make_float2(v00, v01);
            if (ge1 < E_TOT)
                *(float2*)(out + (size_t)ge1 * 32 + oc) = make_float2(v10, v11);
        }
    }
}

extern "C" void kernel_launch(void* const* d_in, const int* in_sizes, int n_in,
                              void* d_out, int out_size)
{
    const float* h_w  = (const float*)d_in[1];
    const float* e_vw = (const float*)d_in[2];
    const float* W0   = (const float*)d_in[3];
    const float* b0   = (const float*)d_in[4];
    const float* W1   = (const float*)d_in[5];
    const float* b1   = (const float*)d_in[6];
    const float* W2   = (const float*)d_in[7];
    const float* b2   = (const float*)d_in[8];
    float* out = (float*)d_out;

    prep_w<<<72, 256>>>(W0, W1, b0, b1);
    prep_T<<<32, 128>>>(W2, b2);

    cudaFuncSetAttribute(msg_kernel, cudaFuncAttributeMaxDynamicSharedMemorySize, SMEM_BYTES);
    msg_kernel<<<GRID, 256, SMEM_BYTES>>>(h_w, e_vw, out);
}

// round 6
// speedup vs baseline: 28.0692x; 1.7059x over previous
#include <cuda_runtime.h>
#include <cuda_bf16.h>
#include <cstdint>

typedef unsigned int u32;

#define E_TOT   200000
#define GRID    148
#define UNITS   12500           // 20 r-values x 625 b-blocks of 16
#define USTRIDE (GRID * 8)

#define OFF_W0H 0
#define OFF_W0L 4096
#define OFF_W1H 8192
#define OFF_W1L 40960
#define OFF_TH  73728
#define OFF_TL  139264
#define OFF_TB  204800
#define OFF_B0  205824
#define OFF_B1  206336
#define SMEM_BYTES 206848

__device__ uint4 gWimg[SMEM_BYTES / 16];

// XOR-swizzled byte offset within a 256B-row bf16 image: row n, col k (0..127)
__host__ __device__ __forceinline__ u32 sw_off(int n, int k) {
    int chunk = k >> 3;
    return (u32)(n * 256 + (((chunk ^ (n & 7)) << 4) | ((k & 7) << 1)));
}

__device__ __forceinline__ void put_hl(u32 offh, u32 offl, u32 boff, float v) {
    char* img = (char*)gWimg;
    __nv_bfloat16 h = __float2bfloat16(v);
    __nv_bfloat16 l = __float2bfloat16(v - __bfloat162float(h));
    *(__nv_bfloat16*)(img + offh + boff) = h;
    *(__nv_bfloat16*)(img + offl + boff) = l;
}

// single prep kernel: blocks 0..71 build W0/W1 images + biases; blocks 72..199
// build the T' table (row n' = m*32 + o, prefix sums over i<4(m+1)) + Tb'.
__global__ void prep(const float* __restrict__ W0, const float* __restrict__ W1,
                     const float* __restrict__ b0, const float* __restrict__ b1,
                     const float* __restrict__ W2, const float* __restrict__ b2)
{
    int blk = blockIdx.x, tid = threadIdx.x;
    if (blk < 72) {
        int id = blk * 256 + tid;
        if (id < 2048) {                   // W0 [128n][16k], 32B rows, no swizzle
            int n = id >> 4, k = id & 15;
            put_hl(OFF_W0H, OFF_W0L, (u32)(n * 32 + k * 2), W0[id]);
        } else if (id < 2048 + 16384) {    // W1 [128n][128k], swizzled
            int j = id - 2048;
            put_hl(OFF_W1H, OFF_W1L, sw_off(j >> 7, j & 127), W1[j]);
        }
        if (id < 128) {
            *(float*)((char*)gWimg + OFF_B0 + id * 4) = b0[id];
            *(float*)((char*)gWimg + OFF_B1 + id * 4) = b1[id];
        }
    } else {
        int row = 2 * (blk - 72) + (tid >> 7);   // 0..255 = m*32 + o
        int m = row >> 5, o = row & 31;
        int j = tid & 127;
        float s = 0.f;
        for (int i = 0; i < 4 * (m + 1); ++i) s += W2[(o * 32 + i) * 128 + j];
        put_hl(OFF_TH, OFF_TL, sw_off(row, j), s);
        if (j == 0) {
            float sb = 0.f;
            for (int i = 0; i < 4 * (m + 1); ++i) sb += b2[o * 32 + i];
            *(float*)((char*)gWimg + OFF_TB + row * 4) = sb;
        }
    }
}

// ---------------------------------------------------------------------------
__device__ __forceinline__ u32 smem_u32(const void* p) {
    u32 a;
    asm("{ .reg .u64 t; cvta.to.shared.u64 t, %1; cvt.u32.u64 %0, t; }" : "=r"(a) : "l"(p));
    return a;
}
__device__ __forceinline__ void ldsm4(u32* r, u32 a) {
    asm volatile("ldmatrix.sync.aligned.m8n8.x4.shared.b16 {%0,%1,%2,%3}, [%4];"
        : "=r"(r[0]), "=r"(r[1]), "=r"(r[2]), "=r"(r[3]) : "r"(a));
}
__device__ __forceinline__ void mma(float* d, const u32* a, const u32* b) {
    asm volatile("mma.sync.aligned.m16n8k16.row.col.f32.bf16.bf16.f32 "
        "{%0,%1,%2,%3}, {%4,%5,%6,%7}, {%8,%9}, {%0,%1,%2,%3};"
        : "+f"(d[0]), "+f"(d[1]), "+f"(d[2]), "+f"(d[3])
        : "r"(a[0]), "r"(a[1]), "r"(a[2]), "r"(a[3]), "r"(b[0]), "r"(b[1]));
}
__device__ __forceinline__ u32 packhl(float f0, float f1, u32& lo) {
    u32 h;
    asm("cvt.rn.bf16x2.f32 %0, %1, %2;" : "=r"(h) : "f"(f1), "f"(f0));
    float h0 = __uint_as_float(h << 16);
    float h1 = __uint_as_float(h & 0xffff0000u);
    asm("cvt.rn.bf16x2.f32 %0, %1, %2;" : "=r"(lo) : "f"(f1 - h1), "f"(f0 - h0));
    return h;
}
__device__ __forceinline__ float relu(float x) { return fmaxf(x, 0.f); }

__global__ void __launch_bounds__(256, 1)
msg_kernel(const float* __restrict__ h_w, const float* __restrict__ e_vw,
           float* __restrict__ out)
{
    extern __shared__ unsigned char sraw[];
    const int t = threadIdx.x, w = t >> 5, lane = t & 31;
    const int lr = lane & 7, g = lane >> 3, q = lane & 3;
    const int kc = 2 * q;
    const int el = lane >> 2;        // edge row within warp tile (0..7); +8 pair

    // stage weight image (202KB)
    {
        uint4* dst = (uint4*)sraw;
        for (int i = t; i < SMEM_BYTES / 16; i += 256) dst[i] = gWimg[i];
    }
    __syncthreads();

    const u32 sb = smem_u32(sraw);
    const float* b0s = (const float*)(sraw + OFF_B0);
    const float* b1s = (const float*)(sraw + OFF_B1);
    const float* Tbs = (const float*)(sraw + OFF_TB);

    for (int u = blockIdx.x * 8 + w; u < UNITS; u += USTRIDE) {
        const int r = u % 20, bblk = u / 20;
        const int nb0 = bblk * 16 + el;      // node of edge ge0
        const int nb1 = nb0 + 8;
        const size_t ge0 = (size_t)nb0 * 20 + r;
        const size_t ge1 = (size_t)nb1 * 20 + r;

        // ---- warp-uniform telescoping structure from r ----
        const int rm = (r * 32) % 20;
        const int i1 = rm ? 20 - rm : 20;
        const int v0 = (r * 32) / 20;
        const int mA = (i1 >> 2) - 1;
        const bool hasB = (i1 + 20) < 32;
        const int mB = hasB ? ((i1 + 20) >> 2) - 1 : 7;

        // ---- per-edge coefficients from h_w ----
        float h00 = h_w[nb0 * 32 + v0], h01 = h_w[nb0 * 32 + v0 + 1];
        float h10 = h_w[nb1 * 32 + v0], h11 = h_w[nb1 * 32 + v0 + 1];
        float cA0 = h00 - h01, cA1 = h10 - h11;
        float cB0 = 0.f, cB1 = 0.f, c70 = h01, c71 = h11;
        if (hasB) {
            float h02 = h_w[nb0 * 32 + v0 + 2], h12 = h_w[nb1 * 32 + v0 + 2];
            cB0 = h01 - h02; cB1 = h11 - h12; c70 = h02; c71 = h12;
        }

        // ---- e fragments (A of GEMM0), hi/lo split ----
        float2 u0 = *(const float2*)(e_vw + ge0 * 16 + kc);
        float2 v0f = *(const float2*)(e_vw + ge0 * 16 + kc + 8);
        float2 u1 = *(const float2*)(e_vw + ge1 * 16 + kc);
        float2 v1f = *(const float2*)(e_vw + ge1 * 16 + kc + 8);
        u32 ah[4], al[4];
        ah[0] = packhl(u0.x, u0.y, al[0]);
        ah[1] = packhl(u1.x, u1.y, al[1]);
        ah[2] = packhl(v0f.x, v0f.y, al[2]);
        ah[3] = packhl(v1f.x, v1f.y, al[3]);

        // ---- GEMM0: x1acc = e @ W0^T (K=16), 3 split products ----
        float acc[64];
        #pragma unroll
        for (int i = 0; i < 64; ++i) acc[i] = 0.f;
        #pragma unroll
        for (int ntp = 0; ntp < 8; ++ntp) {
            int n = (2 * ntp + (g >> 1)) * 8 + lr;
            u32 ad = sb + OFF_W0H + n * 32 + (g & 1) * 16;
            u32 bh[4], bl[4];
            ldsm4(bh, ad);
            ldsm4(bl, ad + (OFF_W0L - OFF_W0H));
            mma(acc + 8 * ntp,     ah, bh);
            mma(acc + 8 * ntp,     ah, bl);
            mma(acc + 8 * ntp,     al, bh);
            mma(acc + 8 * ntp + 4, ah, bh + 2);
            mma(acc + 8 * ntp + 4, ah, bl + 2);
            mma(acc + 8 * ntp + 4, al, bh + 2);
        }

        // ---- bias + relu -> x1 A-fragments ----
        u32 x1h[8][4], x1l[8][4];
        #pragma unroll
        for (int s = 0; s < 8; ++s) {
            int n0 = 16 * s + kc;
            float bb00 = b0s[n0], bb01 = b0s[n0 + 1], bb10 = b0s[n0 + 8], bb11 = b0s[n0 + 9];
            const float* A = acc + 8 * s;
            x1h[s][0] = packhl(relu(A[0] + bb00), relu(A[1] + bb01), x1l[s][0]);
            x1h[s][1] = packhl(relu(A[2] + bb00), relu(A[3] + bb01), x1l[s][1]);
            x1h[s][2] = packhl(relu(A[4] + bb10), relu(A[5] + bb11), x1l[s][2]);
            x1h[s][3] = packhl(relu(A[6] + bb10), relu(A[7] + bb11), x1l[s][3]);
        }

        // ---- GEMM1: x2acc = x1 @ W1^T (K=128) ----
        #pragma unroll
        for (int i = 0; i < 64; ++i) acc[i] = 0.f;
        #pragma unroll
        for (int ntp = 0; ntp < 8; ++ntp) {
            int n = (2 * ntp + (g >> 1)) * 8 + lr;
            u32 rb = sb + OFF_W1H + n * 256;
            u32 sx = (u32)(n & 7) << 4;
            #pragma unroll
            for (int s = 0; s < 8; ++s) {
                u32 ad = rb + (((u32)(2 * s + (g & 1)) << 4) ^ sx);
                u32 bh[4], bl[4];
                ldsm4(bh, ad);
                ldsm4(bl, ad + (OFF_W1L - OFF_W1H));
                mma(acc + 8 * ntp,     x1h[s], bh);
                mma(acc + 8 * ntp,     x1h[s], bl);
                mma(acc + 8 * ntp,     x1l[s], bh);
                mma(acc + 8 * ntp + 4, x1h[s], bh + 2);
                mma(acc + 8 * ntp + 4, x1h[s], bl + 2);
                mma(acc + 8 * ntp + 4, x1l[s], bh + 2);
            }
        }

        // ---- bias + relu -> x2 fragments ----
        u32 x2h[8][4], x2l[8][4];
        #pragma unroll
        for (int s = 0; s < 8; ++s) {
            int n0 = 16 * s + kc;
            float bb00 = b1s[n0], bb01 = b1s[n0 + 1], bb10 = b1s[n0 + 8], bb11 = b1s[n0 + 9];
            const float* A = acc + 8 * s;
            x2h[s][0] = packhl(relu(A[0] + bb00), relu(A[1] + bb01), x2l[s][0]);
            x2h[s][1] = packhl(relu(A[2] + bb00), relu(A[3] + bb01), x2l[s][1]);
            x2h[s][2] = packhl(relu(A[4] + bb10), relu(A[5] + bb11), x2l[s][2]);
            x2h[s][3] = packhl(relu(A[6] + bb10), relu(A[7] + bb11), x2l[s][3]);
        }

        // ---- GEMM_D over only the needed m-groups (warp-uniform) ----
        int   mlist[3] = { mA, 7, mB };
        float c0l[3]   = { cA0, c70, cB0 };
        float c1l[3]   = { cA1, c71, cB1 };
        const int ng = hasB ? 3 : 2;

        float vout0[8], vout1[8];
        #pragma unroll
        for (int i = 0; i < 8; ++i) { vout0[i] = 0.f; vout1[i] = 0.f; }

        for (int grp = 0; grp < ng; ++grp) {
            const int m = mlist[grp];
            const float c0 = c0l[grp], c1 = c1l[grp];
            float accd[16];
            #pragma unroll
            for (int i = 0; i < 16; ++i) accd[i] = 0.f;
            #pragma unroll
            for (int ntp = 0; ntp < 2; ++ntp) {
                int n = m * 32 + (2 * ntp + (g >> 1)) * 8 + lr;
                u32 rb = sb + OFF_TH + n * 256;
                u32 sx = (u32)(n & 7) << 4;
                #pragma unroll
                for (int s = 0; s < 8; ++s) {
                    u32 ad = rb + (((u32)(2 * s + (g & 1)) << 4) ^ sx);
                    u32 bh[4], bl[4];
                    ldsm4(bh, ad);
                    ldsm4(bl, ad + (OFF_TL - OFF_TH));
                    mma(accd + 8 * ntp,     x2h[s], bh);
                    mma(accd + 8 * ntp,     x2h[s], bl);
                    mma(accd + 8 * ntp,     x2l[s], bh);
                    mma(accd + 8 * ntp + 4, x2h[s], bh + 2);
                    mma(accd + 8 * ntp + 4, x2h[s], bl + 2);
                    mma(accd + 8 * ntp + 4, x2l[s], bh + 2);
                }
            }
            // accumulate: o = 16*ntp + 8*tile + 2q + col
            #pragma unroll
            for (int ntp = 0; ntp < 2; ++ntp)
                #pragma unroll
                for (int tile = 0; tile < 2; ++tile) {
                    int o = 16 * ntp + 8 * tile + kc;
                    float tb0 = Tbs[m * 32 + o], tb1 = Tbs[m * 32 + o + 1];
                    const float* A = accd + 8 * ntp + 4 * tile;
                    int vi = 4 * ntp + 2 * tile;
                    vout0[vi]     = fmaf(c0, A[0] + tb0, vout0[vi]);
                    vout0[vi + 1] = fmaf(c0, A[1] + tb1, vout0[vi + 1]);
                    vout1[vi]     = fmaf(c1, A[2] + tb0, vout1[vi]);
                    vout1[vi + 1] = fmaf(c1, A[3] + tb1, vout1[vi + 1]);
                }
        }

        // ---- store: out[e, 16*ntp + 8*tile + 2q + {0,1}] ----
        #pragma unroll
        for (int ntp = 0; ntp < 2; ++ntp)
            #pragma unroll
            for (int tile = 0; tile < 2; ++tile) {
                int o = 16 * ntp + 8 * tile + kc;
                int vi = 4 * ntp + 2 * tile;
                *(float2*)(out + ge0 * 32 + o) = make_float2(vout0[vi], vout0[vi + 1]);
                *(float2*)(out + ge1 * 32 + o) = make_float2(vout1[vi], vout1[vi + 1]);
            }
    }
}

extern "C" void kernel_launch(void* const* d_in, const int* in_sizes, int n_in,
                              void* d_out, int out_size)
{
    const float* h_w  = (const float*)d_in[1];
    const float* e_vw = (const float*)d_in[2];
    const float* W0   = (const float*)d_in[3];
    const float* b0   = (const float*)d_in[4];
    const float* W1   = (const float*)d_in[5];
    const float* b1   = (const float*)d_in[6];
    const float* W2   = (const float*)d_in[7];
    const float* b2   = (const float*)d_in[8];
    float* out = (float*)d_out;

    prep<<<200, 256>>>(W0, W1, b0, b1, W2, b2);

    cudaFuncSetAttribute(msg_kernel, cudaFuncAttributeMaxDynamicSharedMemorySize, SMEM_BYTES);
    msg_kernel<<<GRID, 256, SMEM_BYTES>>>(h_w, e_vw, out);
}